// round 3
// baseline (speedup 1.0000x reference)
#include <cuda_runtime.h>
#include <cuda_bf16.h>

// LIF scan: out[b,0,h]=0; for k=1..T-1:
//   reset = (V_prev > 1)
//   V     = 0.9*V_prev + z[b,k-1,h] - reset
//   out[b,k,h] = (V > 1) ? 1 : 0
//
// One thread per (b,h) chain (16384 threads). Software-pipelined register
// ring (PF=64) keeps ~55+ loads in flight per warp so DRAM latency is hidden
// despite only ~4 warps/SM.

#define B 32
#define T 1024
#define H 512
#define BETA 0.9f
#define THR 1.0f
#define PF 64

__global__ __launch_bounds__(64, 1)
void lif_kernel(const float* __restrict__ z, float* __restrict__ out) {
    const int tid = blockIdx.x * blockDim.x + threadIdx.x;  // 0..16383
    const int b = tid >> 9;          // tid / 512
    const int h = tid & 511;         // tid % 512

    const float* zp = z   + (size_t)b * T * H + h;
    float*       op = out + (size_t)b * T * H + h;

    // k = 0 output is zero (d_out is poisoned, must write).
    op[0] = 0.0f;

    // Prime the ring: loads for input indices 0..PF-1 (all < 1023).
    float buf[PF];
    #pragma unroll
    for (int i = 0; i < PF; ++i)
        buf[i] = zp[i * H];

    float V = 0.0f;

    // 1023 steps total: input index j = 0..1022 feeds output k = j+1.
    const int NSTEP = T - 1;  // 1023
    for (int base = 0; base < NSTEP; base += PF) {
        #pragma unroll
        for (int u = 0; u < PF; ++u) {
            const int j = base + u;
            if (j < NSTEP) {
                float zin = buf[u];
                // Re-issue this slot's load for iteration j+PF (predicated off
                // near the tail). Reuse distance = PF iters -> latency hidden.
                const int jp = j + PF;
                if (jp < NSTEP)
                    buf[u] = zp[jp * H];

                float inj = (V > THR) ? (zin - THR) : zin;  // z - reset*thr
                V = fmaf(BETA, V, inj);
                op[(j + 1) * H] = (V > THR) ? 1.0f : 0.0f;
            }
        }
    }
}

extern "C" void kernel_launch(void* const* d_in, const int* in_sizes, int n_in,
                              void* d_out, int out_size) {
    const float* z = (const float*)d_in[0];
    float* out = (float*)d_out;
    lif_kernel<<<(B * H) / 64, 64>>>(z, out);
}

// round 4
// speedup vs baseline: 13.5915x; 13.5915x over previous
#include <cuda_runtime.h>
#include <cuda_pipeline.h>

// LIF scan, cp.async-pipelined.
//   out[b,0,h] = 0
//   for k=1..T-1: reset=(V>1); V = 0.9V + z[b,k-1,h] - reset; out[b,k,h] = (V>1)
//
// Block = 128 threads <-> 128 h-chains; grid = 32 b * 4 h-tiles = 128 blocks.
// z staged through a 16-deep cp.async pipeline (8 t-steps / stage, 4KB each),
// so DRAM latency is hidden by group-counted completion instead of the 6
// scoreboard slots that killed the register-ring version.

#define Bb    32
#define T     1024
#define Hh    512
#define BETA  0.9f
#define THR   1.0f

#define HT      128   // h per block
#define SROWS   8     // t-steps per stage
#define NSTAGE  16    // pipeline depth (64 KB smem)
#define NSTEP   (T - 1)        // 1023 valid steps
#define NSTAGES_TOT (T / SROWS) // 128 stages, rows 0..1023 all in-bounds

__global__ __launch_bounds__(HT, 1)
void lif_kernel(const float* __restrict__ z, float* __restrict__ out) {
    __shared__ float sbuf[NSTAGE][SROWS][HT];

    const int tid = threadIdx.x;
    const int b   = blockIdx.x >> 2;
    const int h0  = (blockIdx.x & 3) * HT;

    const float* zb = z + (size_t)b * T * Hh + h0;
    float* ob = out + (size_t)b * T * Hh + h0 + tid;

    // loader mapping: thread covers row r = tid/16, cols 8*(tid%16)..+7 (32B)
    const int lr = tid >> 4;
    const int lc = (tid & 15) * 8;

    // k = 0 output is zero (d_out poisoned).
    ob[0] = 0.0f;

    // ── prologue: fill 15 stages ──────────────────────────────────────────
    #pragma unroll
    for (int s = 0; s < NSTAGE - 1; ++s) {
        const float* src = zb + (size_t)(s * SROWS + lr) * Hh + lc;
        __pipeline_memcpy_async(&sbuf[s][lr][lc],     src,     16);
        __pipeline_memcpy_async(&sbuf[s][lr][lc + 4], src + 4, 16);
        __pipeline_commit();
    }

    float V = 0.0f;

    // ── main loop over 128 stages ─────────────────────────────────────────
    for (int s = 0; s < NSTAGES_TOT; ++s) {
        __pipeline_wait_prior(NSTAGE - 2);   // stage s resident
        __syncthreads();                     // cross-thread visibility

        const int slot = s & (NSTAGE - 1);
        const int jbase = s * SROWS;

        if (jbase + SROWS <= NSTEP) {
            #pragma unroll
            for (int r = 0; r < SROWS; ++r) {
                float zin = sbuf[slot][r][tid];
                float inj = (V > THR) ? (zin - THR) : zin;
                V = fmaf(BETA, V, inj);
                ob[(size_t)(jbase + r + 1) * Hh] = (V > THR) ? 1.0f : 0.0f;
            }
        } else {
            #pragma unroll
            for (int r = 0; r < SROWS; ++r) {
                if (jbase + r < NSTEP) {
                    float zin = sbuf[slot][r][tid];
                    float inj = (V > THR) ? (zin - THR) : zin;
                    V = fmaf(BETA, V, inj);
                    ob[(size_t)(jbase + r + 1) * Hh] = (V > THR) ? 1.0f : 0.0f;
                }
            }
        }

        // refill the slot just freed (stage s+NSTAGE-1); always commit so the
        // wait_prior group arithmetic stays uniform.
        const int sn = s + NSTAGE - 1;
        if (sn < NSTAGES_TOT) {
            const float* src = zb + (size_t)(sn * SROWS + lr) * Hh + lc;
            const int dslot = sn & (NSTAGE - 1);
            __pipeline_memcpy_async(&sbuf[dslot][lr][lc],     src,     16);
            __pipeline_memcpy_async(&sbuf[dslot][lr][lc + 4], src + 4, 16);
        }
        __pipeline_commit();
    }
}

extern "C" void kernel_launch(void* const* d_in, const int* in_sizes, int n_in,
                              void* d_out, int out_size) {
    const float* z = (const float*)d_in[0];
    float* out = (float*)d_out;
    lif_kernel<<<(Bb * Hh) / HT, HT>>>(z, out);
}